// round 7
// baseline (speedup 1.0000x reference)
#include <cuda_runtime.h>
#include <math.h>

// Problem constants
#define TT  8192          // seq_len
#define INS 512           // input_size
#define MD  128           // hidden = mem dim
#define CS  64            // chunk size
#define NCH (TT/CS)       // 128 chunks
#define MMD (MD*MD)       // 16384

// ---------------- scratch (device globals; no allocation allowed) ----------------
__device__ __align__(16) float g_q [TT*MD];
__device__ __align__(16) float g_k [TT*MD];
__device__ __align__(16) float g_v [TT*MD];
__device__ __align__(16) float g_og[TT*MD];
__device__ __align__(16) float g_ig[TT];      // exp input gate
__device__ __align__(16) float g_a [TT];      // log f
__device__ __align__(16) float g_L [TT];      // within-chunk inclusive cumsum of log f
__device__ __align__(16) float g_b [TT];      // i_j * exp(A_c - L_j)
__device__ __align__(16) float g_A [NCH];     // chunk totals of log f
__device__ __align__(16) float g_dC[NCH*MMD]; // per-chunk  V^T diag(b) K
__device__ __align__(16) float g_dn[NCH*MD];  // per-chunk  K^T b
__device__ __align__(16) float g_Cst[NCH*MMD];// state at START of each chunk
__device__ __align__(16) float g_nst[NCH*MD];

// ---------------- Kernel 1: projections q,k,v,og  (X[8192,512] @ W[128,512]^T) ---
// grid (TT/128, 1, 4), block 256.  Tile 128(t) x 128(n), K-step 16, 8x8 per thread.
__global__ void __launch_bounds__(256, 2)
proj_kernel(const float* __restrict__ x,
            const float* __restrict__ Wq, const float* __restrict__ bq,
            const float* __restrict__ Wk, const float* __restrict__ bk,
            const float* __restrict__ Wv, const float* __restrict__ bv,
            const float* __restrict__ Wo, const float* __restrict__ bo)
{
    int mode = blockIdx.z;
    const float* W; const float* bias; float* outp;
    if      (mode == 0) { W = Wq; bias = bq; outp = g_q;  }
    else if (mode == 1) { W = Wk; bias = bk; outp = g_k;  }
    else if (mode == 2) { W = Wv; bias = bv; outp = g_v;  }
    else                { W = Wo; bias = bo; outp = g_og; }

    __shared__ float As[128][17];
    __shared__ float Bs[128][17];

    int tid = threadIdx.x;
    int tx = tid & 15, ty = tid >> 4;
    int t0 = blockIdx.x * 128;

    // per-thread load coords: 128 rows x 16 cols = 2048 floats, 8 per thread
    int lrow = tid >> 1;              // 0..127
    int lcol = (tid & 1) * 8;         // 0 or 8

    float acc[8][8];
#pragma unroll
    for (int i = 0; i < 8; i++)
#pragma unroll
        for (int j = 0; j < 8; j++) acc[i][j] = 0.f;

    for (int k0 = 0; k0 < INS; k0 += 16) {
        { // As: 128x16 from x
            float4 a0 = *reinterpret_cast<const float4*>(&x[(t0 + lrow) * INS + k0 + lcol]);
            float4 a1 = *reinterpret_cast<const float4*>(&x[(t0 + lrow) * INS + k0 + lcol + 4]);
            As[lrow][lcol]     = a0.x; As[lrow][lcol + 1] = a0.y;
            As[lrow][lcol + 2] = a0.z; As[lrow][lcol + 3] = a0.w;
            As[lrow][lcol + 4] = a1.x; As[lrow][lcol + 5] = a1.y;
            As[lrow][lcol + 6] = a1.z; As[lrow][lcol + 7] = a1.w;
        }
        { // Bs: 128x16 from W
            float4 b0 = *reinterpret_cast<const float4*>(&W[lrow * INS + k0 + lcol]);
            float4 b1 = *reinterpret_cast<const float4*>(&W[lrow * INS + k0 + lcol + 4]);
            Bs[lrow][lcol]     = b0.x; Bs[lrow][lcol + 1] = b0.y;
            Bs[lrow][lcol + 2] = b0.z; Bs[lrow][lcol + 3] = b0.w;
            Bs[lrow][lcol + 4] = b1.x; Bs[lrow][lcol + 5] = b1.y;
            Bs[lrow][lcol + 6] = b1.z; Bs[lrow][lcol + 7] = b1.w;
        }
        __syncthreads();
#pragma unroll
        for (int kk = 0; kk < 16; kk++) {
            float ar[8], br[8];
#pragma unroll
            for (int i = 0; i < 8; i++) ar[i] = As[ty + i * 16][kk];
#pragma unroll
            for (int j = 0; j < 8; j++) br[j] = Bs[tx + j * 16][kk];
#pragma unroll
            for (int i = 0; i < 8; i++)
#pragma unroll
                for (int j = 0; j < 8; j++) acc[i][j] = fmaf(ar[i], br[j], acc[i][j]);
        }
        __syncthreads();
    }

    const float kscale = 0.08838834764831845f; // 1/sqrt(128)
#pragma unroll
    for (int i = 0; i < 8; i++) {
        int t = t0 + ty + i * 16;
#pragma unroll
        for (int j = 0; j < 8; j++) {
            int n = tx + j * 16;
            float val = acc[i][j] + bias[n];
            if (mode == 1) val *= kscale;
            else if (mode == 3) val = 1.f / (1.f + expf(-val));
            outp[t * MD + n] = val;
        }
    }
}

// ---------------- Kernel 2: scalar gates i = exp(x.wi+bi), a = logsigmoid(x.wf+bf)
// grid TT/8 blocks, block 256 (8 warps; warp per timestep)
__global__ void gate_kernel(const float* __restrict__ x,
                            const float* __restrict__ wi, const float* __restrict__ bi,
                            const float* __restrict__ wf, const float* __restrict__ bf)
{
    int warp = threadIdx.x >> 5, lane = threadIdx.x & 31;
    int t = blockIdx.x * 8 + warp;
    const float* xr = x + t * INS;
    float si = 0.f, sf = 0.f;
#pragma unroll
    for (int c = lane; c < INS; c += 32) {
        float xv = xr[c];
        si = fmaf(xv, wi[c], si);
        sf = fmaf(xv, wf[c], sf);
    }
#pragma unroll
    for (int off = 16; off; off >>= 1) {
        si += __shfl_down_sync(0xffffffffu, si, off);
        sf += __shfl_down_sync(0xffffffffu, sf, off);
    }
    if (lane == 0) {
        g_ig[t] = expf(si + bi[0]);
        float z = sf + bf[0];
        g_a[t] = (z >= 0.f) ? -log1pf(expf(-z)) : (z - log1pf(expf(z)));
    }
}

// ---------------- Kernel 3: per-chunk inclusive scan of log f; b_j ----------------
// grid NCH blocks, block CS
__global__ void scan_kernel()
{
    __shared__ float sh[CS];
    int c = blockIdx.x, j = threadIdx.x;
    int t = c * CS + j;
    sh[j] = g_a[t];
    __syncthreads();
#pragma unroll
    for (int off = 1; off < CS; off <<= 1) {
        float v = (j >= off) ? sh[j - off] : 0.f;
        __syncthreads();
        sh[j] += v;
        __syncthreads();
    }
    float L = sh[j];
    float A = sh[CS - 1];
    g_L[t] = L;
    g_b[t] = g_ig[t] * expf(A - L);
    if (j == 0) g_A[c] = A;
}

// ---------------- Kernel 4: per-chunk dC = V^T diag(b) K,  dn = K^T b -------------
// grid NCH blocks, block 256.  Output 128x128, inner dim j=64 in tiles of 16.
__global__ void __launch_bounds__(256, 2)
dstate_kernel()
{
    __shared__ float Vs[16][129];
    __shared__ float Ks[16][129];
    int c = blockIdx.x;
    int t0 = c * CS;
    int tid = threadIdx.x, tx = tid & 15, ty = tid >> 4;

    float acc[8][8];
#pragma unroll
    for (int i = 0; i < 8; i++)
#pragma unroll
        for (int j = 0; j < 8; j++) acc[i][j] = 0.f;

    for (int j0 = 0; j0 < CS; j0 += 16) {
        int e = tid * 8;
        int jj = e >> 7, r = e & 127;
        float bj = g_b[t0 + j0 + jj];
        float4 v0 = *reinterpret_cast<const float4*>(&g_v[(t0 + j0 + jj) * MD + r]);
        float4 v1 = *reinterpret_cast<const float4*>(&g_v[(t0 + j0 + jj) * MD + r + 4]);
        float4 k0 = *reinterpret_cast<const float4*>(&g_k[(t0 + j0 + jj) * MD + r]);
        float4 k1 = *reinterpret_cast<const float4*>(&g_k[(t0 + j0 + jj) * MD + r + 4]);
        Vs[jj][r] = bj*v0.x; Vs[jj][r+1] = bj*v0.y; Vs[jj][r+2] = bj*v0.z; Vs[jj][r+3] = bj*v0.w;
        Vs[jj][r+4] = bj*v1.x; Vs[jj][r+5] = bj*v1.y; Vs[jj][r+6] = bj*v1.z; Vs[jj][r+7] = bj*v1.w;
        Ks[jj][r] = k0.x; Ks[jj][r+1] = k0.y; Ks[jj][r+2] = k0.z; Ks[jj][r+3] = k0.w;
        Ks[jj][r+4] = k1.x; Ks[jj][r+5] = k1.y; Ks[jj][r+6] = k1.z; Ks[jj][r+7] = k1.w;
        __syncthreads();
#pragma unroll
        for (int jj2 = 0; jj2 < 16; jj2++) {
            float vr[8], kr[8];
#pragma unroll
            for (int i = 0; i < 8; i++) vr[i] = Vs[jj2][ty + i * 16];
#pragma unroll
            for (int j = 0; j < 8; j++) kr[j] = Ks[jj2][tx + j * 16];
#pragma unroll
            for (int i = 0; i < 8; i++)
#pragma unroll
                for (int j = 0; j < 8; j++) acc[i][j] = fmaf(vr[i], kr[j], acc[i][j]);
        }
        __syncthreads();
    }
    float* dC = g_dC + c * MMD;
#pragma unroll
    for (int i = 0; i < 8; i++)
#pragma unroll
        for (int j = 0; j < 8; j++)
            dC[(ty + i * 16) * MD + tx + j * 16] = acc[i][j];

    if (tid < MD) {
        float s = 0.f;
        for (int j = 0; j < CS; j++)
            s = fmaf(g_b[t0 + j], g_k[(t0 + j) * MD + tid], s);
        g_dn[c * MD + tid] = s;
    }
}

// ---------------- Kernel 5: sequential cross-chunk combine (elementwise-parallel) -
// grid MMD/256 blocks, block 256.  Also writes final C_f, n_f into d_out.
__global__ void combine_kernel(const float* __restrict__ C0, const float* __restrict__ n0,
                               float* __restrict__ d_out)
{
    __shared__ float eA[NCH];
    if (threadIdx.x < NCH) eA[threadIdx.x] = expf(g_A[threadIdx.x]);
    __syncthreads();

    int e = blockIdx.x * 256 + threadIdx.x;
    float cv = C0[e];
    for (int c = 0; c < NCH; c++) {
        g_Cst[c * MMD + e] = cv;
        cv = fmaf(eA[c], cv, g_dC[c * MMD + e]);
    }
    d_out[TT + e] = cv;        // C_f
    if (e < MD) {
        float nv = n0[e];
        for (int c = 0; c < NCH; c++) {
            g_nst[c * MD + e] = nv;
            nv = fmaf(eA[c], nv, g_dn[c * MD + e]);
        }
        d_out[TT + MMD + e] = nv;  // n_f
    }
}

// ---------------- Kernel 6: per-chunk output -------------------------------------
// grid NCH blocks, block 256.
//   S = Q K^T (64x64), P = mask*decay*S; raw = P V + diag(exp L) Q Cst^T (64x128)
//   d_t = expL_t*(n_start.q_t) + rowsum(P);  out_t = fc_w . (og*raw/max(|d|,1)) + fc_b
__global__ void __launch_bounds__(256, 2)
output_kernel(const float* __restrict__ fcw, const float* __restrict__ fcb,
              float* __restrict__ d_out)
{
    __shared__ float Ps[CS][CS + 1];       // 64x65
    __shared__ float tA[64 * 17];          // Q tiles [64][17]
    __shared__ float tB[128 * 17];         // K / Cst / V tiles
    __shared__ float Ls[CS], eLs[CS], isv[CS], drow[CS], nq[CS];

    int c = blockIdx.x, t0 = c * CS;
    int tid = threadIdx.x, tx = tid & 15, ty = tid >> 4;
    const float* Cst = g_Cst + c * MMD;
    const float* nst = g_nst + c * MD;

    if (tid < CS) {
        float L = g_L[t0 + tid];
        Ls[tid] = L;
        eLs[tid] = expf(L);
        isv[tid] = g_ig[t0 + tid];
        float s = 0.f;
        const float* qr = &g_q[(t0 + tid) * MD];
        for (int cc = 0; cc < MD; cc++) s = fmaf(nst[cc], qr[cc], s);
        nq[tid] = s;
    }
    __syncthreads();

    // ---- scores S = Q K^T ----
    {
        float sacc[4][4];
#pragma unroll
        for (int i = 0; i < 4; i++)
#pragma unroll
            for (int j = 0; j < 4; j++) sacc[i][j] = 0.f;

        for (int c0 = 0; c0 < MD; c0 += 16) {
            int e = tid * 4;
            int row = e >> 4, col = e & 15;
            float4 qv = *reinterpret_cast<const float4*>(&g_q[(t0 + row) * MD + c0 + col]);
            tA[row * 17 + col] = qv.x; tA[row * 17 + col + 1] = qv.y;
            tA[row * 17 + col + 2] = qv.z; tA[row * 17 + col + 3] = qv.w;
            float4 kv = *reinterpret_cast<const float4*>(&g_k[(t0 + row) * MD + c0 + col]);
            tB[row * 17 + col] = kv.x; tB[row * 17 + col + 1] = kv.y;
            tB[row * 17 + col + 2] = kv.z; tB[row * 17 + col + 3] = kv.w;
            __syncthreads();
#pragma unroll
            for (int cc = 0; cc < 16; cc++) {
                float qr[4], kr[4];
#pragma unroll
                for (int i = 0; i < 4; i++) qr[i] = tA[(ty + i * 16) * 17 + cc];
#pragma unroll
                for (int j = 0; j < 4; j++) kr[j] = tB[(tx + j * 16) * 17 + cc];
#pragma unroll
                for (int i = 0; i < 4; i++)
#pragma unroll
                    for (int j = 0; j < 4; j++) sacc[i][j] = fmaf(qr[i], kr[j], sacc[i][j]);
            }
            __syncthreads();
        }
        // mask + decay -> P; deterministic rowsum via 16-lane shfl
#pragma unroll
        for (int i = 0; i < 4; i++) {
            int t = ty + i * 16;
            float rs = 0.f;
#pragma unroll
            for (int j = 0; j < 4; j++) {
                int jj = tx + j * 16;
                float p = 0.f;
                if (jj <= t) p = sacc[i][j] * isv[jj] * expf(Ls[t] - Ls[jj]);
                Ps[t][jj] = p;
                rs += p;
            }
#pragma unroll
            for (int off = 8; off; off >>= 1) rs += __shfl_down_sync(0xffffffffu, rs, off, 16);
            if (tx == 0) drow[t] = rs;
        }
    }
    __syncthreads();

    // ---- raw = diag(exp L) * (Q Cst^T)  then  += P V ----
    float acc[4][8];
#pragma unroll
    for (int i = 0; i < 4; i++)
#pragma unroll
        for (int j = 0; j < 8; j++) acc[i][j] = 0.f;

    for (int c0 = 0; c0 < MD; c0 += 16) {
        { // Q tile 64x16
            int e = tid * 4;
            int row = e >> 4, col = e & 15;
            float4 qv = *reinterpret_cast<const float4*>(&g_q[(t0 + row) * MD + c0 + col]);
            tA[row * 17 + col] = qv.x; tA[row * 17 + col + 1] = qv.y;
            tA[row * 17 + col + 2] = qv.z; tA[row * 17 + col + 3] = qv.w;
        }
        { // Cst tile 128x16
            int row = tid >> 1, col0 = (tid & 1) * 8;
            float4 a0 = *reinterpret_cast<const float4*>(&Cst[row * MD + c0 + col0]);
            float4 a1 = *reinterpret_cast<const float4*>(&Cst[row * MD + c0 + col0 + 4]);
            tB[row * 17 + col0]     = a0.x; tB[row * 17 + col0 + 1] = a0.y;
            tB[row * 17 + col0 + 2] = a0.z; tB[row * 17 + col0 + 3] = a0.w;
            tB[row * 17 + col0 + 4] = a1.x; tB[row * 17 + col0 + 5] = a1.y;
            tB[row * 17 + col0 + 6] = a1.z; tB[row * 17 + col0 + 7] = a1.w;
        }
        __syncthreads();
#pragma unroll
        for (int cc = 0; cc < 16; cc++) {
            float qr[4], cr[8];
#pragma unroll
            for (int i = 0; i < 4; i++) qr[i] = tA[(ty + i * 16) * 17 + cc];
#pragma unroll
            for (int j = 0; j < 8; j++) cr[j] = tB[(tx + j * 16) * 17 + cc];
#pragma unroll
            for (int i = 0; i < 4; i++)
#pragma unroll
                for (int j = 0; j < 8; j++) acc[i][j] = fmaf(qr[i], cr[j], acc[i][j]);
        }
        __syncthreads();
    }
#pragma unroll
    for (int i = 0; i < 4; i++) {
        float e = eLs[ty + i * 16];
#pragma unroll
        for (int j = 0; j < 8; j++) acc[i][j] *= e;
    }

    for (int j0 = 0; j0 < CS; j0 += 16) {
        { // V tile [16][128] into tB as [16][129]
            int e = tid * 8;
            int jj = e >> 7, r0 = e & 127;
            float4 v0 = *reinterpret_cast<const float4*>(&g_v[(t0 + j0 + jj) * MD + r0]);
            float4 v1 = *reinterpret_cast<const float4*>(&g_v[(t0 + j0 + jj) * MD + r0 + 4]);
            tB[jj * 129 + r0]     = v0.x; tB[jj * 129 + r0 + 1] = v0.y;
            tB[jj * 129 + r0 + 2] = v0.z; tB[jj * 129 + r0 + 3] = v0.w;
            tB[jj * 129 + r0 + 4] = v1.x; tB[jj * 129 + r0 + 5] = v1.y;
            tB[jj * 129 + r0 + 6] = v1.z; tB[jj * 129 + r0 + 7] = v1.w;
        }
        __syncthreads();
#pragma unroll
        for (int jj2 = 0; jj2 < 16; jj2++) {
            float pr[4], vr[8];
#pragma unroll
            for (int i = 0; i < 4; i++) pr[i] = Ps[ty + i * 16][j0 + jj2];
#pragma unroll
            for (int j = 0; j < 8; j++) vr[j] = tB[jj2 * 129 + tx + j * 16];
#pragma unroll
            for (int i = 0; i < 4; i++)
#pragma unroll
                for (int j = 0; j < 8; j++) acc[i][j] = fmaf(pr[i], vr[j], acc[i][j]);
        }
        __syncthreads();
    }

    // ---- finalize: h = og*raw/max(|d|,1); out = fc_w.h + fc_b ----
#pragma unroll
    for (int i = 0; i < 4; i++) {
        int t = ty + i * 16;
        float d = fmaf(eLs[t], nq[t], drow[t]);
        float inv = 1.f / fmaxf(fabsf(d), 1.f);
        float po = 0.f;
#pragma unroll
        for (int j = 0; j < 8; j++) {
            int r = tx + j * 16;
            float h = g_og[(t0 + t) * MD + r] * acc[i][j] * inv;
            po = fmaf(fcw[r], h, po);
        }
#pragma unroll
        for (int off = 8; off; off >>= 1) po += __shfl_down_sync(0xffffffffu, po, off, 16);
        if (tx == 0) d_out[t0 + t] = po + fcb[0];
    }
}

// ---------------- launch ----------------------------------------------------------
extern "C" void kernel_launch(void* const* d_in, const int* in_sizes, int n_in,
                              void* d_out, int out_size)
{
    const float* x   = (const float*)d_in[0];
    const float* C0  = (const float*)d_in[1];
    const float* n0  = (const float*)d_in[2];
    const float* Wq  = (const float*)d_in[3];
    const float* bq  = (const float*)d_in[4];
    const float* Wk  = (const float*)d_in[5];
    const float* bk  = (const float*)d_in[6];
    const float* Wv  = (const float*)d_in[7];
    const float* bv  = (const float*)d_in[8];
    const float* wi  = (const float*)d_in[9];
    const float* bi  = (const float*)d_in[10];
    const float* wf  = (const float*)d_in[11];
    const float* bf  = (const float*)d_in[12];
    const float* Wo  = (const float*)d_in[13];
    const float* bo  = (const float*)d_in[14];
    const float* fcw = (const float*)d_in[15];
    const float* fcb = (const float*)d_in[16];
    float* out = (float*)d_out;

    proj_kernel<<<dim3(TT / 128, 1, 4), 256>>>(x, Wq, bq, Wk, bk, Wv, bv, Wo, bo);
    gate_kernel<<<TT / 8, 256>>>(x, wi, bi, wf, bf);
    scan_kernel<<<NCH, CS>>>();
    dstate_kernel<<<NCH, 256>>>();
    combine_kernel<<<MMD / 256, 256>>>(C0, n0, out);
    output_kernel<<<NCH, 256>>>(fcw, fcb, out);
}

// round 12
// speedup vs baseline: 1.3191x; 1.3191x over previous
#include <cuda_runtime.h>
#include <cuda_bf16.h>
#include <math.h>
#include <stdint.h>

// Problem constants
#define TT  8192          // seq_len
#define INS 512           // input_size
#define MD  128           // hidden = mem dim
#define CS  64            // chunk size
#define NCH (TT/CS)       // 128 chunks
#define MMD (MD*MD)       // 16384

// ---------------- scratch (device globals; no allocation allowed) ----------------
__device__ __align__(16) float g_q [TT*MD];
__device__ __align__(16) float g_k [TT*MD];
__device__ __align__(16) float g_v [TT*MD];
__device__ __align__(16) float g_og[TT*MD];
__device__ __align__(16) float g_ig[TT];
__device__ __align__(16) float g_a [TT];
__device__ __align__(16) float g_L [TT];
__device__ __align__(16) float g_b [TT];
__device__ __align__(16) float g_A [NCH];
__device__ __align__(16) float g_dC[NCH*MMD];
__device__ __align__(16) float g_dn[NCH*MD];
__device__ __align__(16) float g_Cst[NCH*MMD];
__device__ __align__(16) float g_nst[NCH*MD];
// bf16 split operands for tensor-core projections
__device__ __align__(16) __nv_bfloat16 g_xh[TT*INS];
__device__ __align__(16) __nv_bfloat16 g_xl[TT*INS];
__device__ __align__(16) __nv_bfloat16 g_wh[4*MD*INS];
__device__ __align__(16) __nv_bfloat16 g_wl[4*MD*INS];

// ---------------- Kernel 0a: split x into bf16 hi/lo -----------------------------
__global__ void convert_x_kernel(const float* __restrict__ x)
{
    int i = blockIdx.x * 256 + threadIdx.x;          // float4 index
    float4 v = reinterpret_cast<const float4*>(x)[i];
    float vs[4] = {v.x, v.y, v.z, v.w};
    int b = i * 4;
#pragma unroll
    for (int j = 0; j < 4; j++) {
        __nv_bfloat16 h = __float2bfloat16_rn(vs[j]);
        float r = vs[j] - __bfloat162float(h);
        g_xh[b + j] = h;
        g_xl[b + j] = __float2bfloat16_rn(r);
    }
}

// ---------------- Kernel 0b: split W matrices into bf16 hi/lo --------------------
__global__ void convert_w_kernel(const float* __restrict__ Wq, const float* __restrict__ Wk,
                                 const float* __restrict__ Wv, const float* __restrict__ Wo)
{
    int mode = blockIdx.z;
    const float* W = (mode == 0) ? Wq : (mode == 1) ? Wk : (mode == 2) ? Wv : Wo;
    int i = blockIdx.x * 256 + threadIdx.x;
    float4 v = reinterpret_cast<const float4*>(W)[i];
    float vs[4] = {v.x, v.y, v.z, v.w};
    int b = mode * MD * INS + i * 4;
#pragma unroll
    for (int j = 0; j < 4; j++) {
        __nv_bfloat16 h = __float2bfloat16_rn(vs[j]);
        float r = vs[j] - __bfloat162float(h);
        g_wh[b + j] = h;
        g_wl[b + j] = __float2bfloat16_rn(r);
    }
}

// ---------------- Kernel 1: mma.sync bf16 split-precision projections ------------
// grid (TT/128, 1, 4), block 256 (8 warps: 2m x 4n), warp tile 64x32.
// D = Ah*Bh + Al*Bh + Ah*Bl, fp32 accumulators. K=512 in 32 steps of 16.
__device__ __forceinline__ void mma16816(float* c, const uint32_t* a, const uint32_t* b)
{
    asm volatile(
        "mma.sync.aligned.m16n8k16.row.col.f32.bf16.bf16.f32 "
        "{%0,%1,%2,%3}, {%4,%5,%6,%7}, {%8,%9}, {%0,%1,%2,%3};"
        : "+f"(c[0]), "+f"(c[1]), "+f"(c[2]), "+f"(c[3])
        : "r"(a[0]), "r"(a[1]), "r"(a[2]), "r"(a[3]), "r"(b[0]), "r"(b[1]));
}

__global__ void __launch_bounds__(256)
proj_mma_kernel(const float* __restrict__ bq, const float* __restrict__ bk,
                const float* __restrict__ bv, const float* __restrict__ bo)
{
    // smem tiles as bf16-pairs (uint32), row stride 9 to stagger banks
    __shared__ uint32_t sAh[128][9];
    __shared__ uint32_t sAl[128][9];
    __shared__ uint32_t sBh[128][9];
    __shared__ uint32_t sBl[128][9];

    int tid = threadIdx.x;
    int wid = tid >> 5, lane = tid & 31;
    int gID = lane >> 2, tig = lane & 3;
    int wm = (wid >> 2) * 64;            // warp m offset (0 or 64)
    int wn = (wid & 3) * 32;             // warp n offset (0,32,64,96)
    int mode = blockIdx.z;
    int t0 = blockIdx.x * 128;

    const __nv_bfloat16* xh = g_xh + (size_t)t0 * INS;
    const __nv_bfloat16* xl = g_xl + (size_t)t0 * INS;
    const __nv_bfloat16* wh = g_wh + (size_t)mode * MD * INS;
    const __nv_bfloat16* wl = g_wl + (size_t)mode * MD * INS;
    const float* bias = (mode == 0) ? bq : (mode == 1) ? bk : (mode == 2) ? bv : bo;
    float* outp = (mode == 0) ? g_q : (mode == 1) ? g_k : (mode == 2) ? g_v : g_og;

    // per-thread tile-load coords: 2 threads per row, 8 bf16 (one uint4) each
    int lrow = tid >> 1;
    int lp4  = (tid & 1) * 4;            // pair index 0 or 4
    int lcol = lp4 * 2;                  // bf16 col 0 or 8

    float c[4][4][4];
#pragma unroll
    for (int mf = 0; mf < 4; mf++)
#pragma unroll
        for (int nf = 0; nf < 4; nf++)
#pragma unroll
            for (int q = 0; q < 4; q++) c[mf][nf][q] = 0.f;

    for (int kc = 0; kc < 32; kc++) {
        int kb = kc * 16 + lcol;
        {
            uint4 v = *reinterpret_cast<const uint4*>(xh + (size_t)lrow * INS + kb);
            sAh[lrow][lp4] = v.x; sAh[lrow][lp4+1] = v.y; sAh[lrow][lp4+2] = v.z; sAh[lrow][lp4+3] = v.w;
        }
        {
            uint4 v = *reinterpret_cast<const uint4*>(xl + (size_t)lrow * INS + kb);
            sAl[lrow][lp4] = v.x; sAl[lrow][lp4+1] = v.y; sAl[lrow][lp4+2] = v.z; sAl[lrow][lp4+3] = v.w;
        }
        {
            uint4 v = *reinterpret_cast<const uint4*>(wh + (size_t)lrow * INS + kb);
            sBh[lrow][lp4] = v.x; sBh[lrow][lp4+1] = v.y; sBh[lrow][lp4+2] = v.z; sBh[lrow][lp4+3] = v.w;
        }
        {
            uint4 v = *reinterpret_cast<const uint4*>(wl + (size_t)lrow * INS + kb);
            sBl[lrow][lp4] = v.x; sBl[lrow][lp4+1] = v.y; sBl[lrow][lp4+2] = v.z; sBl[lrow][lp4+3] = v.w;
        }
        __syncthreads();

        uint32_t ah[4][4], bh[4][2], bl[4][2];
#pragma unroll
        for (int mf = 0; mf < 4; mf++) {
            int r0 = wm + mf * 16 + gID;
            ah[mf][0] = sAh[r0][tig];     ah[mf][1] = sAh[r0 + 8][tig];
            ah[mf][2] = sAh[r0][tig + 4]; ah[mf][3] = sAh[r0 + 8][tig + 4];
        }
#pragma unroll
        for (int nf = 0; nf < 4; nf++) {
            int n0 = wn + nf * 8 + gID;
            bh[nf][0] = sBh[n0][tig]; bh[nf][1] = sBh[n0][tig + 4];
            bl[nf][0] = sBl[n0][tig]; bl[nf][1] = sBl[n0][tig + 4];
        }
        // pass 1: Ah * Bh
#pragma unroll
        for (int mf = 0; mf < 4; mf++)
#pragma unroll
            for (int nf = 0; nf < 4; nf++) mma16816(c[mf][nf], ah[mf], bh[nf]);
        // pass 2: Ah * Bl
#pragma unroll
        for (int mf = 0; mf < 4; mf++)
#pragma unroll
            for (int nf = 0; nf < 4; nf++) mma16816(c[mf][nf], ah[mf], bl[nf]);
        // pass 3: Al * Bh (reuse ah storage for al)
#pragma unroll
        for (int mf = 0; mf < 4; mf++) {
            int r0 = wm + mf * 16 + gID;
            ah[mf][0] = sAl[r0][tig];     ah[mf][1] = sAl[r0 + 8][tig];
            ah[mf][2] = sAl[r0][tig + 4]; ah[mf][3] = sAl[r0 + 8][tig + 4];
        }
#pragma unroll
        for (int mf = 0; mf < 4; mf++)
#pragma unroll
            for (int nf = 0; nf < 4; nf++) mma16816(c[mf][nf], ah[mf], bh[nf]);
        __syncthreads();
    }

    // Epilogue: bias + activation + store (float2 per frag row)
    const float kscale = 0.08838834764831845f; // 1/sqrt(128)
#pragma unroll
    for (int mf = 0; mf < 4; mf++) {
#pragma unroll
        for (int nf = 0; nf < 4; nf++) {
            int row = t0 + wm + mf * 16 + gID;
            int col = wn + nf * 8 + tig * 2;
            float b0 = bias[col], b1 = bias[col + 1];
            float v0 = c[mf][nf][0] + b0, v1 = c[mf][nf][1] + b1;
            float v2 = c[mf][nf][2] + b0, v3 = c[mf][nf][3] + b1;
            if (mode == 1) { v0 *= kscale; v1 *= kscale; v2 *= kscale; v3 *= kscale; }
            else if (mode == 3) {
                v0 = 1.f / (1.f + expf(-v0)); v1 = 1.f / (1.f + expf(-v1));
                v2 = 1.f / (1.f + expf(-v2)); v3 = 1.f / (1.f + expf(-v3));
            }
            *reinterpret_cast<float2*>(&outp[(size_t)row * MD + col])       = make_float2(v0, v1);
            *reinterpret_cast<float2*>(&outp[(size_t)(row + 8) * MD + col]) = make_float2(v2, v3);
        }
    }
}

// ---------------- Kernel 2: scalar gates -----------------------------------------
__global__ void gate_kernel(const float* __restrict__ x,
                            const float* __restrict__ wi, const float* __restrict__ bi,
                            const float* __restrict__ wf, const float* __restrict__ bf)
{
    int warp = threadIdx.x >> 5, lane = threadIdx.x & 31;
    int t = blockIdx.x * 8 + warp;
    const float* xr = x + t * INS;
    float si = 0.f, sf = 0.f;
#pragma unroll
    for (int c = lane; c < INS; c += 32) {
        float xv = xr[c];
        si = fmaf(xv, wi[c], si);
        sf = fmaf(xv, wf[c], sf);
    }
#pragma unroll
    for (int off = 16; off; off >>= 1) {
        si += __shfl_down_sync(0xffffffffu, si, off);
        sf += __shfl_down_sync(0xffffffffu, sf, off);
    }
    if (lane == 0) {
        g_ig[t] = expf(si + bi[0]);
        float z = sf + bf[0];
        g_a[t] = (z >= 0.f) ? -log1pf(expf(-z)) : (z - log1pf(expf(z)));
    }
}

// ---------------- Kernel 3: per-chunk inclusive scan of log f --------------------
__global__ void scan_kernel()
{
    __shared__ float sh[CS];
    int c = blockIdx.x, j = threadIdx.x;
    int t = c * CS + j;
    sh[j] = g_a[t];
    __syncthreads();
#pragma unroll
    for (int off = 1; off < CS; off <<= 1) {
        float v = (j >= off) ? sh[j - off] : 0.f;
        __syncthreads();
        sh[j] += v;
        __syncthreads();
    }
    float L = sh[j];
    float A = sh[CS - 1];
    g_L[t] = L;
    g_b[t] = g_ig[t] * expf(A - L);
    if (j == 0) g_A[c] = A;
}

// ---------------- Kernel 4: per-chunk dC = V^T diag(b) K,  dn = K^T b ------------
__global__ void __launch_bounds__(256, 2)
dstate_kernel()
{
    __shared__ float Vs[16][129];
    __shared__ float Ks[16][129];
    int c = blockIdx.x;
    int t0 = c * CS;
    int tid = threadIdx.x, tx = tid & 15, ty = tid >> 4;

    float acc[8][8];
#pragma unroll
    for (int i = 0; i < 8; i++)
#pragma unroll
        for (int j = 0; j < 8; j++) acc[i][j] = 0.f;

    for (int j0 = 0; j0 < CS; j0 += 16) {
        int e = tid * 8;
        int jj = e >> 7, r = e & 127;
        float bj = g_b[t0 + j0 + jj];
        float4 v0 = *reinterpret_cast<const float4*>(&g_v[(t0 + j0 + jj) * MD + r]);
        float4 v1 = *reinterpret_cast<const float4*>(&g_v[(t0 + j0 + jj) * MD + r + 4]);
        float4 k0 = *reinterpret_cast<const float4*>(&g_k[(t0 + j0 + jj) * MD + r]);
        float4 k1 = *reinterpret_cast<const float4*>(&g_k[(t0 + j0 + jj) * MD + r + 4]);
        Vs[jj][r] = bj*v0.x; Vs[jj][r+1] = bj*v0.y; Vs[jj][r+2] = bj*v0.z; Vs[jj][r+3] = bj*v0.w;
        Vs[jj][r+4] = bj*v1.x; Vs[jj][r+5] = bj*v1.y; Vs[jj][r+6] = bj*v1.z; Vs[jj][r+7] = bj*v1.w;
        Ks[jj][r] = k0.x; Ks[jj][r+1] = k0.y; Ks[jj][r+2] = k0.z; Ks[jj][r+3] = k0.w;
        Ks[jj][r+4] = k1.x; Ks[jj][r+5] = k1.y; Ks[jj][r+6] = k1.z; Ks[jj][r+7] = k1.w;
        __syncthreads();
#pragma unroll
        for (int jj2 = 0; jj2 < 16; jj2++) {
            float vr[8], kr[8];
#pragma unroll
            for (int i = 0; i < 8; i++) vr[i] = Vs[jj2][ty + i * 16];
#pragma unroll
            for (int j = 0; j < 8; j++) kr[j] = Ks[jj2][tx + j * 16];
#pragma unroll
            for (int i = 0; i < 8; i++)
#pragma unroll
                for (int j = 0; j < 8; j++) acc[i][j] = fmaf(vr[i], kr[j], acc[i][j]);
        }
        __syncthreads();
    }
    float* dC = g_dC + c * MMD;
#pragma unroll
    for (int i = 0; i < 8; i++)
#pragma unroll
        for (int j = 0; j < 8; j++)
            dC[(ty + i * 16) * MD + tx + j * 16] = acc[i][j];

    if (tid < MD) {
        float s = 0.f;
        for (int j = 0; j < CS; j++)
            s = fmaf(g_b[t0 + j], g_k[(t0 + j) * MD + tid], s);
        g_dn[c * MD + tid] = s;
    }
}

// ---------------- Kernel 5: sequential cross-chunk combine -----------------------
__global__ void combine_kernel(const float* __restrict__ C0, const float* __restrict__ n0,
                               float* __restrict__ d_out)
{
    __shared__ float eA[NCH];
    if (threadIdx.x < NCH) eA[threadIdx.x] = expf(g_A[threadIdx.x]);
    __syncthreads();

    int e = blockIdx.x * 256 + threadIdx.x;
    float cv = C0[e];
    for (int c = 0; c < NCH; c++) {
        g_Cst[c * MMD + e] = cv;
        cv = fmaf(eA[c], cv, g_dC[c * MMD + e]);
    }
    d_out[TT + e] = cv;        // C_f
    if (e < MD) {
        float nv = n0[e];
        for (int c = 0; c < NCH; c++) {
            g_nst[c * MD + e] = nv;
            nv = fmaf(eA[c], nv, g_dn[c * MD + e]);
        }
        d_out[TT + MMD + e] = nv;  // n_f
    }
}

// ---------------- Kernel 6: per-chunk output -------------------------------------
__global__ void __launch_bounds__(256, 2)
output_kernel(const float* __restrict__ fcw, const float* __restrict__ fcb,
              float* __restrict__ d_out)
{
    __shared__ float Ps[CS][CS + 1];
    __shared__ float tA[64 * 17];
    __shared__ float tB[128 * 17];
    __shared__ float Ls[CS], eLs[CS], isv[CS], drow[CS], nq[CS];

    int c = blockIdx.x, t0 = c * CS;
    int tid = threadIdx.x, tx = tid & 15, ty = tid >> 4;
    const float* Cst = g_Cst + c * MMD;
    const float* nst = g_nst + c * MD;

    if (tid < CS) {
        float L = g_L[t0 + tid];
        Ls[tid] = L;
        eLs[tid] = expf(L);
        isv[tid] = g_ig[t0 + tid];
        float s = 0.f;
        const float* qr = &g_q[(t0 + tid) * MD];
        for (int cc = 0; cc < MD; cc++) s = fmaf(nst[cc], qr[cc], s);
        nq[tid] = s;
    }
    __syncthreads();

    {
        float sacc[4][4];
#pragma unroll
        for (int i = 0; i < 4; i++)
#pragma unroll
            for (int j = 0; j < 4; j++) sacc[i][j] = 0.f;

        for (int c0 = 0; c0 < MD; c0 += 16) {
            int e = tid * 4;
            int row = e >> 4, col = e & 15;
            float4 qv = *reinterpret_cast<const float4*>(&g_q[(t0 + row) * MD + c0 + col]);
            tA[row * 17 + col] = qv.x; tA[row * 17 + col + 1] = qv.y;
            tA[row * 17 + col + 2] = qv.z; tA[row * 17 + col + 3] = qv.w;
            float4 kv = *reinterpret_cast<const float4*>(&g_k[(t0 + row) * MD + c0 + col]);
            tB[row * 17 + col] = kv.x; tB[row * 17 + col + 1] = kv.y;
            tB[row * 17 + col + 2] = kv.z; tB[row * 17 + col + 3] = kv.w;
            __syncthreads();
#pragma unroll
            for (int cc = 0; cc < 16; cc++) {
                float qr[4], kr[4];
#pragma unroll
                for (int i = 0; i < 4; i++) qr[i] = tA[(ty + i * 16) * 17 + cc];
#pragma unroll
                for (int j = 0; j < 4; j++) kr[j] = tB[(tx + j * 16) * 17 + cc];
#pragma unroll
                for (int i = 0; i < 4; i++)
#pragma unroll
                    for (int j = 0; j < 4; j++) sacc[i][j] = fmaf(qr[i], kr[j], sacc[i][j]);
            }
            __syncthreads();
        }
#pragma unroll
        for (int i = 0; i < 4; i++) {
            int t = ty + i * 16;
            float rs = 0.f;
#pragma unroll
            for (int j = 0; j < 4; j++) {
                int jj = tx + j * 16;
                float p = 0.f;
                if (jj <= t) p = sacc[i][j] * isv[jj] * expf(Ls[t] - Ls[jj]);
                Ps[t][jj] = p;
                rs += p;
            }
#pragma unroll
            for (int off = 8; off; off >>= 1) rs += __shfl_down_sync(0xffffffffu, rs, off, 16);
            if (tx == 0) drow[t] = rs;
        }
    }
    __syncthreads();

    float acc[4][8];
#pragma unroll
    for (int i = 0; i < 4; i++)
#pragma unroll
        for (int j = 0; j < 8; j++) acc[i][j] = 0.f;

    for (int c0 = 0; c0 < MD; c0 += 16) {
        {
            int e = tid * 4;
            int row = e >> 4, col = e & 15;
            float4 qv = *reinterpret_cast<const float4*>(&g_q[(t0 + row) * MD + c0 + col]);
            tA[row * 17 + col] = qv.x; tA[row * 17 + col + 1] = qv.y;
            tA[row * 17 + col + 2] = qv.z; tA[row * 17 + col + 3] = qv.w;
        }
        {
            int row = tid >> 1, col0 = (tid & 1) * 8;
            float4 a0 = *reinterpret_cast<const float4*>(&Cst[row * MD + c0 + col0]);
            float4 a1 = *reinterpret_cast<const float4*>(&Cst[row * MD + c0 + col0 + 4]);
            tB[row * 17 + col0]     = a0.x; tB[row * 17 + col0 + 1] = a0.y;
            tB[row * 17 + col0 + 2] = a0.z; tB[row * 17 + col0 + 3] = a0.w;
            tB[row * 17 + col0 + 4] = a1.x; tB[row * 17 + col0 + 5] = a1.y;
            tB[row * 17 + col0 + 6] = a1.z; tB[row * 17 + col0 + 7] = a1.w;
        }
        __syncthreads();
#pragma unroll
        for (int cc = 0; cc < 16; cc++) {
            float qr[4], cr[8];
#pragma unroll
            for (int i = 0; i < 4; i++) qr[i] = tA[(ty + i * 16) * 17 + cc];
#pragma unroll
            for (int j = 0; j < 8; j++) cr[j] = tB[(tx + j * 16) * 17 + cc];
#pragma unroll
            for (int i = 0; i < 4; i++)
#pragma unroll
                for (int j = 0; j < 8; j++) acc[i][j] = fmaf(qr[i], cr[j], acc[i][j]);
        }
        __syncthreads();
    }
#pragma unroll
    for (int i = 0; i < 4; i++) {
        float e = eLs[ty + i * 16];
#pragma unroll
        for (int j = 0; j < 8; j++) acc[i][j] *= e;
    }

    for (int j0 = 0; j0 < CS; j0 += 16) {
        {
            int e = tid * 8;
            int jj = e >> 7, r0 = e & 127;
            float4 v0 = *reinterpret_cast<const float4*>(&g_v[(t0 + j0 + jj) * MD + r0]);
            float4 v1 = *reinterpret_cast<const float4*>(&g_v[(t0 + j0 + jj) * MD + r0 + 4]);
            tB[jj * 129 + r0]     = v0.x; tB[jj * 129 + r0 + 1] = v0.y;
            tB[jj * 129 + r0 + 2] = v0.z; tB[jj * 129 + r0 + 3] = v0.w;
            tB[jj * 129 + r0 + 4] = v1.x; tB[jj * 129 + r0 + 5] = v1.y;
            tB[jj * 129 + r0 + 6] = v1.z; tB[jj * 129 + r0 + 7] = v1.w;
        }
        __syncthreads();
#pragma unroll
        for (int jj2 = 0; jj2 < 16; jj2++) {
            float pr[4], vr[8];
#pragma unroll
            for (int i = 0; i < 4; i++) pr[i] = Ps[ty + i * 16][j0 + jj2];
#pragma unroll
            for (int j = 0; j < 8; j++) vr[j] = tB[jj2 * 129 + tx + j * 16];
#pragma unroll
            for (int i = 0; i < 4; i++)
#pragma unroll
                for (int j = 0; j < 8; j++) acc[i][j] = fmaf(pr[i], vr[j], acc[i][j]);
        }
        __syncthreads();
    }

#pragma unroll
    for (int i = 0; i < 4; i++) {
        int t = ty + i * 16;
        float d = fmaf(eLs[t], nq[t], drow[t]);
        float inv = 1.f / fmaxf(fabsf(d), 1.f);
        float po = 0.f;
#pragma unroll
        for (int j = 0; j < 8; j++) {
            int r = tx + j * 16;
            float h = g_og[(t0 + t) * MD + r] * acc[i][j] * inv;
            po = fmaf(fcw[r], h, po);
        }
#pragma unroll
        for (int off = 8; off; off >>= 1) po += __shfl_down_sync(0xffffffffu, po, off, 16);
        if (tx == 0) d_out[t0 + t] = po + fcb[0];
    }
}

// ---------------- launch ----------------------------------------------------------
extern "C" void kernel_launch(void* const* d_in, const int* in_sizes, int n_in,
                              void* d_out, int out_size)
{
    const float* x   = (const float*)d_in[0];
    const float* C0  = (const float*)d_in[1];
    const float* n0  = (const float*)d_in[2];
    const float* Wq  = (const float*)d_in[3];
    const float* bq  = (const float*)d_in[4];
    const float* Wk  = (const float*)d_in[5];
    const float* bk  = (const float*)d_in[6];
    const float* Wv  = (const float*)d_in[7];
    const float* bv  = (const float*)d_in[8];
    const float* wi  = (const float*)d_in[9];
    const float* bi  = (const float*)d_in[10];
    const float* wf  = (const float*)d_in[11];
    const float* bf  = (const float*)d_in[12];
    const float* Wo  = (const float*)d_in[13];
    const float* bo  = (const float*)d_in[14];
    const float* fcw = (const float*)d_in[15];
    const float* fcb = (const float*)d_in[16];
    float* out = (float*)d_out;

    convert_x_kernel<<<TT * INS / 4 / 256, 256>>>(x);
    convert_w_kernel<<<dim3(MD * INS / 4 / 256, 1, 4), 256>>>(Wq, Wk, Wv, Wo);
    proj_mma_kernel<<<dim3(TT / 128, 1, 4), 256>>>(bq, bk, bv, bo);
    gate_kernel<<<TT / 8, 256>>>(x, wi, bi, wf, bf);
    scan_kernel<<<NCH, CS>>>();
    dstate_kernel<<<NCH, 256>>>();
    combine_kernel<<<MMD / 256, 256>>>(C0, n0, out);
    output_kernel<<<NCH, 256>>>(fcw, fcb, out);
}

// round 16
// speedup vs baseline: 1.4047x; 1.0648x over previous
#include <cuda_runtime.h>
#include <cuda_bf16.h>
#include <math.h>
#include <stdint.h>

// Problem constants
#define TT  8192          // seq_len
#define INS 512           // input_size
#define MD  128           // hidden = mem dim
#define CS  64            // chunk size
#define NCH (TT/CS)       // 128 chunks
#define MMD (MD*MD)       // 16384

// ---------------- scratch (device globals; no allocation allowed) ----------------
__device__ __align__(16) float g_q [TT*MD];
__device__ __align__(16) float g_k [TT*MD];
__device__ __align__(16) float g_v [TT*MD];
__device__ __align__(16) float g_og[TT*MD];
__device__ __align__(16) float g_ig[TT];
__device__ __align__(16) float g_a [TT];
__device__ __align__(16) float g_L [TT];
__device__ __align__(16) float g_b [TT];
__device__ __align__(16) float g_A [NCH];
__device__ __align__(16) float g_dC[NCH*MMD];
__device__ __align__(16) float g_dn[NCH*MD];
__device__ __align__(16) float g_Cst[NCH*MMD];
__device__ __align__(16) float g_nst[NCH*MD];
// bf16 split operands for tensor-core projections
__device__ __align__(16) __nv_bfloat16 g_xh[TT*INS];
__device__ __align__(16) __nv_bfloat16 g_xl[TT*INS];
__device__ __align__(16) __nv_bfloat16 g_wh[4*MD*INS];
__device__ __align__(16) __nv_bfloat16 g_wl[4*MD*INS];

// ---------------- Kernel 0a: split x into bf16 hi/lo -----------------------------
__global__ void convert_x_kernel(const float* __restrict__ x)
{
    int i = blockIdx.x * 256 + threadIdx.x;          // float4 index
    float4 v = reinterpret_cast<const float4*>(x)[i];
    float vs[4] = {v.x, v.y, v.z, v.w};
    int b = i * 4;
#pragma unroll
    for (int j = 0; j < 4; j++) {
        __nv_bfloat16 h = __float2bfloat16_rn(vs[j]);
        float r = vs[j] - __bfloat162float(h);
        g_xh[b + j] = h;
        g_xl[b + j] = __float2bfloat16_rn(r);
    }
}

// ---------------- Kernel 0b: split W matrices into bf16 hi/lo --------------------
__global__ void convert_w_kernel(const float* __restrict__ Wq, const float* __restrict__ Wk,
                                 const float* __restrict__ Wv, const float* __restrict__ Wo)
{
    int mode = blockIdx.z;
    const float* W = (mode == 0) ? Wq : (mode == 1) ? Wk : (mode == 2) ? Wv : Wo;
    int i = blockIdx.x * 256 + threadIdx.x;
    float4 v = reinterpret_cast<const float4*>(W)[i];
    float vs[4] = {v.x, v.y, v.z, v.w};
    int b = mode * MD * INS + i * 4;
#pragma unroll
    for (int j = 0; j < 4; j++) {
        __nv_bfloat16 h = __float2bfloat16_rn(vs[j]);
        float r = vs[j] - __bfloat162float(h);
        g_wh[b + j] = h;
        g_wl[b + j] = __float2bfloat16_rn(r);
    }
}

// ---------------- Kernel 1: mma.sync bf16 split-precision projections ------------
// grid (TT/128, 1, 4), block 256 (8 warps: 2m x 4n), warp tile 64x32.
// D = Ah*Bh + Al*Bh + Ah*Bl, fp32 accumulators. K=512 in 32 steps of 16.
// Double-buffered cp.async tile loads; row stride 12 uint32 (48 B) keeps every
// 16B cp.async destination aligned AND makes fragment LDS bank-conflict-free
// (12g+tig mod 32 hits all 32 banks).
#define RS 12
__device__ __forceinline__ void mma16816(float* c, const uint32_t* a, const uint32_t* b)
{
    asm volatile(
        "mma.sync.aligned.m16n8k16.row.col.f32.bf16.bf16.f32 "
        "{%0,%1,%2,%3}, {%4,%5,%6,%7}, {%8,%9}, {%0,%1,%2,%3};"
        : "+f"(c[0]), "+f"(c[1]), "+f"(c[2]), "+f"(c[3])
        : "r"(a[0]), "r"(a[1]), "r"(a[2]), "r"(a[3]), "r"(b[0]), "r"(b[1]));
}

__device__ __forceinline__ void cp16(uint32_t dst_smem, const void* src) {
    asm volatile("cp.async.cg.shared.global [%0], [%1], 16;" :: "r"(dst_smem), "l"(src) : "memory");
}

__global__ void __launch_bounds__(256, 2)
proj_mma_kernel(const float* __restrict__ bq, const float* __restrict__ bk,
                const float* __restrict__ bv, const float* __restrict__ bo)
{
    // double-buffered smem tiles as bf16-pairs (uint32), row stride RS=12
    __shared__ __align__(16) uint32_t sAh[2][128][RS];
    __shared__ __align__(16) uint32_t sAl[2][128][RS];
    __shared__ __align__(16) uint32_t sBh[2][128][RS];
    __shared__ __align__(16) uint32_t sBl[2][128][RS];

    int tid = threadIdx.x;
    int wid = tid >> 5, lane = tid & 31;
    int gID = lane >> 2, tig = lane & 3;
    int wm = (wid >> 2) * 64;            // warp m offset (0 or 64)
    int wn = (wid & 3) * 32;             // warp n offset (0,32,64,96)
    int mode = blockIdx.z;
    int t0 = blockIdx.x * 128;

    const __nv_bfloat16* xh = g_xh + (size_t)t0 * INS;
    const __nv_bfloat16* xl = g_xl + (size_t)t0 * INS;
    const __nv_bfloat16* wh = g_wh + (size_t)mode * MD * INS;
    const __nv_bfloat16* wl = g_wl + (size_t)mode * MD * INS;
    const float* bias = (mode == 0) ? bq : (mode == 1) ? bk : (mode == 2) ? bv : bo;
    float* outp = (mode == 0) ? g_q : (mode == 1) ? g_k : (mode == 2) ? g_v : g_og;

    // per-thread tile-load coords: 2 threads per row, 8 bf16 (one uint4) each
    int lrow = tid >> 1;
    int lp4  = (tid & 1) * 4;            // word index 0 or 4 (byte 0 or 16, both 16B-aligned)
    int lcol = lp4 * 2;                  // bf16 col 0 or 8
    size_t goff = (size_t)lrow * INS;    // global row offset (elements)

    // per-thread smem destinations (generic->shared, constant across iterations)
    uint32_t dAh[2], dAl[2], dBh[2], dBl[2];
#pragma unroll
    for (int b = 0; b < 2; b++) {
        dAh[b] = (uint32_t)__cvta_generic_to_shared(&sAh[b][lrow][lp4]);
        dAl[b] = (uint32_t)__cvta_generic_to_shared(&sAl[b][lrow][lp4]);
        dBh[b] = (uint32_t)__cvta_generic_to_shared(&sBh[b][lrow][lp4]);
        dBl[b] = (uint32_t)__cvta_generic_to_shared(&sBl[b][lrow][lp4]);
    }

    float c[4][4][4];
#pragma unroll
    for (int mf = 0; mf < 4; mf++)
#pragma unroll
        for (int nf = 0; nf < 4; nf++)
#pragma unroll
            for (int q = 0; q < 4; q++) c[mf][nf][q] = 0.f;

    // prologue: prefetch k-step 0 into buffer 0
    {
        int kb = lcol;
        cp16(dAh[0], xh + goff + kb);
        cp16(dAl[0], xl + goff + kb);
        cp16(dBh[0], wh + goff + kb);
        cp16(dBl[0], wl + goff + kb);
        asm volatile("cp.async.commit_group;" ::: "memory");
    }

    for (int kc = 0; kc < 32; kc++) {
        int p = kc & 1;
        if (kc + 1 < 32) {
            int kb = (kc + 1) * 16 + lcol;
            int nb = 1 - p;
            cp16(dAh[nb], xh + goff + kb);
            cp16(dAl[nb], xl + goff + kb);
            cp16(dBh[nb], wh + goff + kb);
            cp16(dBl[nb], wl + goff + kb);
            asm volatile("cp.async.commit_group;" ::: "memory");
            asm volatile("cp.async.wait_group 1;" ::: "memory");
        } else {
            asm volatile("cp.async.wait_group 0;" ::: "memory");
        }
        __syncthreads();

        uint32_t ah[4][4], bh[4][2], bl[4][2];
#pragma unroll
        for (int mf = 0; mf < 4; mf++) {
            int r0 = wm + mf * 16 + gID;
            ah[mf][0] = sAh[p][r0][tig];     ah[mf][1] = sAh[p][r0 + 8][tig];
            ah[mf][2] = sAh[p][r0][tig + 4]; ah[mf][3] = sAh[p][r0 + 8][tig + 4];
        }
#pragma unroll
        for (int nf = 0; nf < 4; nf++) {
            int n0 = wn + nf * 8 + gID;
            bh[nf][0] = sBh[p][n0][tig]; bh[nf][1] = sBh[p][n0][tig + 4];
            bl[nf][0] = sBl[p][n0][tig]; bl[nf][1] = sBl[p][n0][tig + 4];
        }
        // pass 1: Ah * Bh
#pragma unroll
        for (int mf = 0; mf < 4; mf++)
#pragma unroll
            for (int nf = 0; nf < 4; nf++) mma16816(c[mf][nf], ah[mf], bh[nf]);
        // pass 2: Ah * Bl
#pragma unroll
        for (int mf = 0; mf < 4; mf++)
#pragma unroll
            for (int nf = 0; nf < 4; nf++) mma16816(c[mf][nf], ah[mf], bl[nf]);
        // pass 3: Al * Bh (reuse ah storage for al)
#pragma unroll
        for (int mf = 0; mf < 4; mf++) {
            int r0 = wm + mf * 16 + gID;
            ah[mf][0] = sAl[p][r0][tig];     ah[mf][1] = sAl[p][r0 + 8][tig];
            ah[mf][2] = sAl[p][r0][tig + 4]; ah[mf][3] = sAl[p][r0 + 8][tig + 4];
        }
#pragma unroll
        for (int mf = 0; mf < 4; mf++)
#pragma unroll
            for (int nf = 0; nf < 4; nf++) mma16816(c[mf][nf], ah[mf], bh[nf]);
        __syncthreads();
    }

    // Epilogue: bias + activation + store (float2 per frag row)
    const float kscale = 0.08838834764831845f; // 1/sqrt(128)
#pragma unroll
    for (int mf = 0; mf < 4; mf++) {
#pragma unroll
        for (int nf = 0; nf < 4; nf++) {
            int row = t0 + wm + mf * 16 + gID;
            int col = wn + nf * 8 + tig * 2;
            float b0 = bias[col], b1 = bias[col + 1];
            float v0 = c[mf][nf][0] + b0, v1 = c[mf][nf][1] + b1;
            float v2 = c[mf][nf][2] + b0, v3 = c[mf][nf][3] + b1;
            if (mode == 1) { v0 *= kscale; v1 *= kscale; v2 *= kscale; v3 *= kscale; }
            else if (mode == 3) {
                v0 = 1.f / (1.f + expf(-v0)); v1 = 1.f / (1.f + expf(-v1));
                v2 = 1.f / (1.f + expf(-v2)); v3 = 1.f / (1.f + expf(-v3));
            }
            *reinterpret_cast<float2*>(&outp[(size_t)row * MD + col])       = make_float2(v0, v1);
            *reinterpret_cast<float2*>(&outp[(size_t)(row + 8) * MD + col]) = make_float2(v2, v3);
        }
    }
}

// ---------------- Kernel 2: scalar gates -----------------------------------------
__global__ void gate_kernel(const float* __restrict__ x,
                            const float* __restrict__ wi, const float* __restrict__ bi,
                            const float* __restrict__ wf, const float* __restrict__ bf)
{
    int warp = threadIdx.x >> 5, lane = threadIdx.x & 31;
    int t = blockIdx.x * 8 + warp;
    const float* xr = x + t * INS;
    float si = 0.f, sf = 0.f;
#pragma unroll
    for (int c = lane; c < INS; c += 32) {
        float xv = xr[c];
        si = fmaf(xv, wi[c], si);
        sf = fmaf(xv, wf[c], sf);
    }
#pragma unroll
    for (int off = 16; off; off >>= 1) {
        si += __shfl_down_sync(0xffffffffu, si, off);
        sf += __shfl_down_sync(0xffffffffu, sf, off);
    }
    if (lane == 0) {
        g_ig[t] = expf(si + bi[0]);
        float z = sf + bf[0];
        g_a[t] = (z >= 0.f) ? -log1pf(expf(-z)) : (z - log1pf(expf(z)));
    }
}

// ---------------- Kernel 3: per-chunk inclusive scan of log f --------------------
__global__ void scan_kernel()
{
    __shared__ float sh[CS];
    int c = blockIdx.x, j = threadIdx.x;
    int t = c * CS + j;
    sh[j] = g_a[t];
    __syncthreads();
#pragma unroll
    for (int off = 1; off < CS; off <<= 1) {
        float v = (j >= off) ? sh[j - off] : 0.f;
        __syncthreads();
        sh[j] += v;
        __syncthreads();
    }
    float L = sh[j];
    float A = sh[CS - 1];
    g_L[t] = L;
    g_b[t] = g_ig[t] * expf(A - L);
    if (j == 0) g_A[c] = A;
}

// ---------------- Kernel 4: per-chunk dC = V^T diag(b) K,  dn = K^T b ------------
__global__ void __launch_bounds__(256, 2)
dstate_kernel()
{
    __shared__ float Vs[16][129];
    __shared__ float Ks[16][129];
    int c = blockIdx.x;
    int t0 = c * CS;
    int tid = threadIdx.x, tx = tid & 15, ty = tid >> 4;

    float acc[8][8];
#pragma unroll
    for (int i = 0; i < 8; i++)
#pragma unroll
        for (int j = 0; j < 8; j++) acc[i][j] = 0.f;

    for (int j0 = 0; j0 < CS; j0 += 16) {
        int e = tid * 8;
        int jj = e >> 7, r = e & 127;
        float bj = g_b[t0 + j0 + jj];
        float4 v0 = *reinterpret_cast<const float4*>(&g_v[(t0 + j0 + jj) * MD + r]);
        float4 v1 = *reinterpret_cast<const float4*>(&g_v[(t0 + j0 + jj) * MD + r + 4]);
        float4 k0 = *reinterpret_cast<const float4*>(&g_k[(t0 + j0 + jj) * MD + r]);
        float4 k1 = *reinterpret_cast<const float4*>(&g_k[(t0 + j0 + jj) * MD + r + 4]);
        Vs[jj][r] = bj*v0.x; Vs[jj][r+1] = bj*v0.y; Vs[jj][r+2] = bj*v0.z; Vs[jj][r+3] = bj*v0.w;
        Vs[jj][r+4] = bj*v1.x; Vs[jj][r+5] = bj*v1.y; Vs[jj][r+6] = bj*v1.z; Vs[jj][r+7] = bj*v1.w;
        Ks[jj][r] = k0.x; Ks[jj][r+1] = k0.y; Ks[jj][r+2] = k0.z; Ks[jj][r+3] = k0.w;
        Ks[jj][r+4] = k1.x; Ks[jj][r+5] = k1.y; Ks[jj][r+6] = k1.z; Ks[jj][r+7] = k1.w;
        __syncthreads();
#pragma unroll
        for (int jj2 = 0; jj2 < 16; jj2++) {
            float vr[8], kr[8];
#pragma unroll
            for (int i = 0; i < 8; i++) vr[i] = Vs[jj2][ty + i * 16];
#pragma unroll
            for (int j = 0; j < 8; j++) kr[j] = Ks[jj2][tx + j * 16];
#pragma unroll
            for (int i = 0; i < 8; i++)
#pragma unroll
                for (int j = 0; j < 8; j++) acc[i][j] = fmaf(vr[i], kr[j], acc[i][j]);
        }
        __syncthreads();
    }
    float* dC = g_dC + c * MMD;
#pragma unroll
    for (int i = 0; i < 8; i++)
#pragma unroll
        for (int j = 0; j < 8; j++)
            dC[(ty + i * 16) * MD + tx + j * 16] = acc[i][j];

    if (tid < MD) {
        float s = 0.f;
        for (int j = 0; j < CS; j++)
            s = fmaf(g_b[t0 + j], g_k[(t0 + j) * MD + tid], s);
        g_dn[c * MD + tid] = s;
    }
}

// ---------------- Kernel 5: sequential cross-chunk combine -----------------------
__global__ void combine_kernel(const float* __restrict__ C0, const float* __restrict__ n0,
                               float* __restrict__ d_out)
{
    __shared__ float eA[NCH];
    if (threadIdx.x < NCH) eA[threadIdx.x] = expf(g_A[threadIdx.x]);
    __syncthreads();

    int e = blockIdx.x * 256 + threadIdx.x;
    float cv = C0[e];
    for (int c = 0; c < NCH; c++) {
        g_Cst[c * MMD + e] = cv;
        cv = fmaf(eA[c], cv, g_dC[c * MMD + e]);
    }
    d_out[TT + e] = cv;        // C_f
    if (e < MD) {
        float nv = n0[e];
        for (int c = 0; c < NCH; c++) {
            g_nst[c * MD + e] = nv;
            nv = fmaf(eA[c], nv, g_dn[c * MD + e]);
        }
        d_out[TT + MMD + e] = nv;  // n_f
    }
}

// ---------------- Kernel 6: per-chunk output -------------------------------------
__global__ void __launch_bounds__(256, 2)
output_kernel(const float* __restrict__ fcw, const float* __restrict__ fcb,
              float* __restrict__ d_out)
{
    __shared__ float Ps[CS][CS + 1];
    __shared__ float tA[64 * 17];
    __shared__ float tB[128 * 17];
    __shared__ float Ls[CS], eLs[CS], isv[CS], drow[CS], nq[CS];

    int c = blockIdx.x, t0 = c * CS;
    int tid = threadIdx.x, tx = tid & 15, ty = tid >> 4;
    const float* Cst = g_Cst + c * MMD;
    const float* nst = g_nst + c * MD;

    if (tid < CS) {
        float L = g_L[t0 + tid];
        Ls[tid] = L;
        eLs[tid] = expf(L);
        isv[tid] = g_ig[t0 + tid];
        float s = 0.f;
        const float* qr = &g_q[(t0 + tid) * MD];
        for (int cc = 0; cc < MD; cc++) s = fmaf(nst[cc], qr[cc], s);
        nq[tid] = s;
    }
    __syncthreads();

    {
        float sacc[4][4];
#pragma unroll
        for (int i = 0; i < 4; i++)
#pragma unroll
            for (int j = 0; j < 4; j++) sacc[i][j] = 0.f;

        for (int c0 = 0; c0 < MD; c0 += 16) {
            int e = tid * 4;
            int row = e >> 4, col = e & 15;
            float4 qv = *reinterpret_cast<const float4*>(&g_q[(t0 + row) * MD + c0 + col]);
            tA[row * 17 + col] = qv.x; tA[row * 17 + col + 1] = qv.y;
            tA[row * 17 + col + 2] = qv.z; tA[row * 17 + col + 3] = qv.w;
            float4 kv = *reinterpret_cast<const float4*>(&g_k[(t0 + row) * MD + c0 + col]);
            tB[row * 17 + col] = kv.x; tB[row * 17 + col + 1] = kv.y;
            tB[row * 17 + col + 2] = kv.z; tB[row * 17 + col + 3] = kv.w;
            __syncthreads();
#pragma unroll
            for (int cc = 0; cc < 16; cc++) {
                float qr[4], kr[4];
#pragma unroll
                for (int i = 0; i < 4; i++) qr[i] = tA[(ty + i * 16) * 17 + cc];
#pragma unroll
                for (int j = 0; j < 4; j++) kr[j] = tB[(tx + j * 16) * 17 + cc];
#pragma unroll
                for (int i = 0; i < 4; i++)
#pragma unroll
                    for (int j = 0; j < 4; j++) sacc[i][j] = fmaf(qr[i], kr[j], sacc[i][j]);
            }
            __syncthreads();
        }
#pragma unroll
        for (int i = 0; i < 4; i++) {
            int t = ty + i * 16;
            float rs = 0.f;
#pragma unroll
            for (int j = 0; j < 4; j++) {
                int jj = tx + j * 16;
                float p = 0.f;
                if (jj <= t) p = sacc[i][j] * isv[jj] * expf(Ls[t] - Ls[jj]);
                Ps[t][jj] = p;
                rs += p;
            }
#pragma unroll
            for (int off = 8; off; off >>= 1) rs += __shfl_down_sync(0xffffffffu, rs, off, 16);
            if (tx == 0) drow[t] = rs;
        }
    }
    __syncthreads();

    float acc[4][8];
#pragma unroll
    for (int i = 0; i < 4; i++)
#pragma unroll
        for (int j = 0; j < 8; j++) acc[i][j] = 0.f;

    for (int c0 = 0; c0 < MD; c0 += 16) {
        {
            int e = tid * 4;
            int row = e >> 4, col = e & 15;
            float4 qv = *reinterpret_cast<const float4*>(&g_q[(t0 + row) * MD + c0 + col]);
            tA[row * 17 + col] = qv.x; tA[row * 17 + col + 1] = qv.y;
            tA[row * 17 + col + 2] = qv.z; tA[row * 17 + col + 3] = qv.w;
        }
        {
            int row = tid >> 1, col0 = (tid & 1) * 8;
            float4 a0 = *reinterpret_cast<const float4*>(&Cst[row * MD + c0 + col0]);
            float4 a1 = *reinterpret_cast<const float4*>(&Cst[row * MD + c0 + col0 + 4]);
            tB[row * 17 + col0]     = a0.x; tB[row * 17 + col0 + 1] = a0.y;
            tB[row * 17 + col0 + 2] = a0.z; tB[row * 17 + col0 + 3] = a0.w;
            tB[row * 17 + col0 + 4] = a1.x; tB[row * 17 + col0 + 5] = a1.y;
            tB[row * 17 + col0 + 6] = a1.z; tB[row * 17 + col0 + 7] = a1.w;
        }
        __syncthreads();
#pragma unroll
        for (int cc = 0; cc < 16; cc++) {
            float qr[4], cr[8];
#pragma unroll
            for (int i = 0; i < 4; i++) qr[i] = tA[(ty + i * 16) * 17 + cc];
#pragma unroll
            for (int j = 0; j < 8; j++) cr[j] = tB[(tx + j * 16) * 17 + cc];
#pragma unroll
            for (int i = 0; i < 4; i++)
#pragma unroll
                for (int j = 0; j < 8; j++) acc[i][j] = fmaf(qr[i], cr[j], acc[i][j]);
        }
        __syncthreads();
    }
#pragma unroll
    for (int i = 0; i < 4; i++) {
        float e = eLs[ty + i * 16];
#pragma unroll
        for (int j = 0; j < 8; j++) acc[i][j] *= e;
    }

    for (int j0 = 0; j0 < CS; j0 += 16) {
        {
            int e = tid * 8;
            int jj = e >> 7, r0 = e & 127;
            float4 v0 = *reinterpret_cast<const float4*>(&g_v[(t0 + j0 + jj) * MD + r0]);
            float4 v1 = *reinterpret_cast<const float4*>(&g_v[(t0 + j0 + jj) * MD + r0 + 4]);
            tB[jj * 129 + r0]     = v0.x; tB[jj * 129 + r0 + 1] = v0.y;
            tB[jj * 129 + r0 + 2] = v0.z; tB[jj * 129 + r0 + 3] = v0.w;
            tB[jj * 129 + r0 + 4] = v1.x; tB[jj * 129 + r0 + 5] = v1.y;
            tB[jj * 129 + r0 + 6] = v1.z; tB[jj * 129 + r0 + 7] = v1.w;
        }
        __syncthreads();
#pragma unroll
        for (int jj2 = 0; jj2 < 16; jj2++) {
            float pr[4], vr[8];
#pragma unroll
            for (int i = 0; i < 4; i++) pr[i] = Ps[ty + i * 16][j0 + jj2];
#pragma unroll
            for (int j = 0; j < 8; j++) vr[j] = tB[jj2 * 129 + tx + j * 16];
#pragma unroll
            for (int i = 0; i < 4; i++)
#pragma unroll
                for (int j = 0; j < 8; j++) acc[i][j] = fmaf(pr[i], vr[j], acc[i][j]);
        }
        __syncthreads();
    }

#pragma unroll
    for (int i = 0; i < 4; i++) {
        int t = ty + i * 16;
        float d = fmaf(eLs[t], nq[t], drow[t]);
        float inv = 1.f / fmaxf(fabsf(d), 1.f);
        float po = 0.f;
#pragma unroll
        for (int j = 0; j < 8; j++) {
            int r = tx + j * 16;
            float h = g_og[(t0 + t) * MD + r] * acc[i][j] * inv;
            po = fmaf(fcw[r], h, po);
        }
#pragma unroll
        for (int off = 8; off; off >>= 1) po += __shfl_down_sync(0xffffffffu, po, off, 16);
        if (tx == 0) d_out[t0 + t] = po + fcb[0];
    }
}

// ---------------- launch ----------------------------------------------------------
extern "C" void kernel_launch(void* const* d_in, const int* in_sizes, int n_in,
                              void* d_out, int out_size)
{
    const float* x   = (const float*)d_in[0];
    const float* C0  = (const float*)d_in[1];
    const float* n0  = (const float*)d_in[2];
    const float* Wq  = (const float*)d_in[3];
    const float* bq  = (const float*)d_in[4];
    const float* Wk  = (const float*)d_in[5];
    const float* bk  = (const float*)d_in[6];
    const float* Wv  = (const float*)d_in[7];
    const float* bv  = (const float*)d_in[8];
    const float* wi  = (const float*)d_in[9];
    const float* bi  = (const float*)d_in[10];
    const float* wf  = (const float*)d_in[11];
    const float* bf  = (const float*)d_in[12];
    const float* Wo  = (const float*)d_in[13];
    const float* bo  = (const float*)d_in[14];
    const float* fcw = (const float*)d_in[15];
    const float* fcb = (const float*)d_in[16];
    float* out = (float*)d_out;

    convert_x_kernel<<<TT * INS / 4 / 256, 256>>>(x);
    convert_w_kernel<<<dim3(MD * INS / 4 / 256, 1, 4), 256>>>(Wq, Wk, Wv, Wo);
    proj_mma_kernel<<<dim3(TT / 128, 1, 4), 256>>>(bq, bk, bv, bo);
    gate_kernel<<<TT / 8, 256>>>(x, wi, bi, wf, bf);
    scan_kernel<<<NCH, CS>>>();
    dstate_kernel<<<NCH, 256>>>();
    combine_kernel<<<MMD / 256, 256>>>(C0, n0, out);
    output_kernel<<<NCH, 256>>>(fcw, fcb, out);
}